// round 1
// baseline (speedup 1.0000x reference)
#include <cuda_runtime.h>
#include <cuda_bf16.h>

// Problem constants (fixed by the dataset): z_e (16,4096,64) f32, embed (1024,64) f32.
#define N_ROWS  65536
#define DIM     64
#define KCODES  1024
#define TC      128        // codes per smem tile
#define THREADS 256
#define NBLOCKS (N_ROWS / THREADS)   // 256

__device__ float g_norms[KCODES];     // ||e_k||^2
__device__ float g_partial[NBLOCKS];  // per-block sum of (z_q - z_e)^2

// ---- packed f32x2 helpers (sm_103a FFMA2 path) ----
__device__ __forceinline__ void fma2(unsigned long long& acc,
                                     unsigned long long a,
                                     unsigned long long b) {
    asm("fma.rn.f32x2 %0, %1, %2, %0;" : "+l"(acc) : "l"(a), "l"(b));
}
__device__ __forceinline__ unsigned long long add2(unsigned long long a,
                                                   unsigned long long b) {
    unsigned long long r;
    asm("add.rn.f32x2 %0, %1, %2;" : "=l"(r) : "l"(a), "l"(b));
    return r;
}
__device__ __forceinline__ float2 unpack2(unsigned long long v) {
    float2 r;
    asm("mov.b64 {%0, %1}, %2;" : "=f"(r.x), "=f"(r.y) : "l"(v));
    return r;
}

// ---- kernel 1: codebook squared norms ----
__global__ void vq_norms_kernel(const float* __restrict__ embed) {
    int k = blockIdx.x * blockDim.x + threadIdx.x;
    if (k < KCODES) {
        const float4* e = reinterpret_cast<const float4*>(embed + (size_t)k * DIM);
        float s = 0.f;
#pragma unroll
        for (int i = 0; i < DIM / 4; ++i) {
            float4 v = e[i];
            s += v.x * v.x + v.y * v.y + v.z * v.z + v.w * v.w;
        }
        g_norms[k] = s;
    }
}

// ---- kernel 2: main VQ argmin + gather + straight-through + loss partials ----
__global__ __launch_bounds__(THREADS, 2)
void vq_main_kernel(const float* __restrict__ z_e,
                    const float* __restrict__ embed,
                    float* __restrict__ out) {
    __shared__ float4 s_codes[TC * (DIM / 4)];  // 32 KB
    __shared__ float  s_ne[TC];
    __shared__ float  s_red[THREADS];

    const int row = blockIdx.x * THREADS + threadIdx.x;

    // Load this thread's row as 32 packed f32x2 values (64 regs).
    unsigned long long x2[DIM / 2];
    {
        const ulonglong2* xr =
            reinterpret_cast<const ulonglong2*>(z_e + (size_t)row * DIM);
#pragma unroll
        for (int i = 0; i < DIM / 4; ++i) {
            ulonglong2 w = xr[i];
            x2[2 * i]     = w.x;
            x2[2 * i + 1] = w.y;
        }
    }

    float best = 3.4e38f;
    int   bidx = 0;

    for (int t = 0; t < KCODES / TC; ++t) {
        __syncthreads();
        // Stage tile of codes + their norms.
        {
            const float4* src = reinterpret_cast<const float4*>(
                embed + (size_t)t * TC * DIM);
#pragma unroll
            for (int i = 0; i < (TC * (DIM / 4)) / THREADS; ++i)
                s_codes[threadIdx.x + i * THREADS] = src[threadIdx.x + i * THREADS];
            if (threadIdx.x < TC)
                s_ne[threadIdx.x] = g_norms[t * TC + threadIdx.x];
        }
        __syncthreads();

        for (int c = 0; c < TC; ++c) {
            const ulonglong2* ce = reinterpret_cast<const ulonglong2*>(
                &s_codes[c * (DIM / 4)]);
            unsigned long long a0 = 0ull, a1 = 0ull;
#pragma unroll
            for (int i = 0; i < DIM / 4; ++i) {
                ulonglong2 w = ce[i];        // LDS.128, warp-broadcast
                fma2(a0, x2[2 * i],     w.x);
                fma2(a1, x2[2 * i + 1], w.y);
            }
            float2 p = unpack2(add2(a0, a1));
            float score = s_ne[c] - 2.0f * (p.x + p.y);
            if (score < best) { best = score; bidx = t * TC + c; }
        }
    }

    // Epilogue: gather code, straight-through output, diff^2 accumulation.
    float sq = 0.f;
    {
        const float4* q = reinterpret_cast<const float4*>(embed + (size_t)bidx * DIM);
        float4* orow = reinterpret_cast<float4*>(out + (size_t)row * DIM);
#pragma unroll
        for (int i = 0; i < DIM / 4; ++i) {
            float4 e = q[i];
            float2 xa = unpack2(x2[2 * i]);
            float2 xb = unpack2(x2[2 * i + 1]);
            float dx = e.x - xa.x, dy = e.y - xa.y;
            float dz = e.z - xb.x, dw = e.w - xb.y;
            sq += dx * dx + dy * dy + dz * dz + dw * dw;
            orow[i] = make_float4(xa.x + dx, xa.y + dy, xb.x + dz, xb.y + dw);
        }
    }
    out[(size_t)N_ROWS * DIM + row] = (float)bidx;

    // Deterministic block reduction of loss partial.
    s_red[threadIdx.x] = sq;
    __syncthreads();
#pragma unroll
    for (int s = THREADS / 2; s > 0; s >>= 1) {
        if (threadIdx.x < s) s_red[threadIdx.x] += s_red[threadIdx.x + s];
        __syncthreads();
    }
    if (threadIdx.x == 0) g_partial[blockIdx.x] = s_red[0];
}

// ---- kernel 3: finalize vq_loss = 1.25 * sum / (N*D) ----
__global__ void vq_finalize_kernel(float* __restrict__ out) {
    __shared__ float s[NBLOCKS];
    s[threadIdx.x] = g_partial[threadIdx.x];
    __syncthreads();
#pragma unroll
    for (int st = NBLOCKS / 2; st > 0; st >>= 1) {
        if (threadIdx.x < st) s[threadIdx.x] += s[threadIdx.x + st];
        __syncthreads();
    }
    if (threadIdx.x == 0) {
        out[(size_t)N_ROWS * DIM + N_ROWS] =
            1.25f * s[0] / (float)((size_t)N_ROWS * DIM);
    }
}

extern "C" void kernel_launch(void* const* d_in, const int* in_sizes, int n_in,
                              void* d_out, int out_size) {
    const float* z_e   = (const float*)d_in[0];
    const float* embed = (const float*)d_in[1];
    float* out = (float*)d_out;
    (void)in_sizes; (void)n_in; (void)out_size;

    vq_norms_kernel<<<KCODES / 256, 256>>>(embed);
    vq_main_kernel<<<NBLOCKS, THREADS>>>(z_e, embed, out);
    vq_finalize_kernel<<<1, NBLOCKS>>>(out);
}

// round 2
// speedup vs baseline: 1.0424x; 1.0424x over previous
#include <cuda_runtime.h>
#include <cuda_bf16.h>

// Problem constants: z_e (16,4096,64) f32, embed (1024,64) f32.
#define N_ROWS   65536
#define DIM      64
#define KCODES   1024
#define TCODES   64                    // codes per tile
#define NTILES   (KCODES / TCODES)     // 16
#define THREADS  64
#define ROWS_PB  64
#define NBLOCKS  (N_ROWS / ROWS_PB)    // 1024
#define XPITCH   68                    // padded floats per k-row (16B aligned, bank drift 4)
#define EPITCH   68

__device__ float g_hne[KCODES];        // -0.5 * ||e_k||^2
__device__ float g_partial[NBLOCKS];

// ---- packed f32x2 helpers ----
__device__ __forceinline__ void fma2(unsigned long long& acc,
                                     unsigned long long a,
                                     unsigned long long b) {
    asm("fma.rn.f32x2 %0, %1, %2, %0;" : "+l"(acc) : "l"(a), "l"(b));
}
__device__ __forceinline__ unsigned long long add2(unsigned long long a,
                                                   unsigned long long b) {
    unsigned long long r;
    asm("add.rn.f32x2 %0, %1, %2;" : "=l"(r) : "l"(a), "l"(b));
    return r;
}
__device__ __forceinline__ float2 unpack2(unsigned long long v) {
    float2 r;
    asm("mov.b64 {%0, %1}, %2;" : "=f"(r.x), "=f"(r.y) : "l"(v));
    return r;
}
__device__ __forceinline__ unsigned long long pack_dup(float v) {
    unsigned long long r;
    asm("mov.b64 %0, {%1, %1};" : "=l"(r) : "f"(v));
    return r;
}

// ---- kernel 1: -0.5 * codebook squared norms ----
__global__ void vq_norms_kernel(const float* __restrict__ embed) {
    int k = blockIdx.x * blockDim.x + threadIdx.x;
    if (k < KCODES) {
        const float4* e = reinterpret_cast<const float4*>(embed + (size_t)k * DIM);
        float s = 0.f;
#pragma unroll
        for (int i = 0; i < DIM / 4; ++i) {
            float4 v = e[i];
            s += v.x * v.x + v.y * v.y + v.z * v.z + v.w * v.w;
        }
        g_hne[k] = -0.5f * s;
    }
}

// ---- kernel 2: register-tiled distance GEMM + argmin + epilogue ----
__global__ __launch_bounds__(THREADS, 6)
void vq_main_kernel(const float* __restrict__ z_e,
                    const float* __restrict__ embed,
                    float* __restrict__ out) {
    __shared__ float x_t[DIM * XPITCH];   // x transposed: [k][row], 17408 B
    __shared__ float e_t[DIM * EPITCH];   // e tile transposed: [k][code], 17408 B
    __shared__ int   s_bidx[ROWS_PB];
    __shared__ float s_red[THREADS];

    const int tid  = threadIdx.x;
    const int lane = tid & 31;
    const int wid  = tid >> 5;
    const int rx   = lane & 3;      // row group within warp (4 groups x 8 rows)
    const int cy   = lane >> 2;     // code group within warp (8 groups x 8 codes)
    const int row0 = blockIdx.x * ROWS_PB;

    // Load + transpose this block's 64 rows of z_e into x_t[k][row].
    {
        const float4* src = reinterpret_cast<const float4*>(
            z_e + (size_t)(row0 + tid) * DIM);
#pragma unroll
        for (int i = 0; i < DIM / 4; ++i) {
            float4 v = src[i];
            x_t[(4 * i + 0) * XPITCH + tid] = v.x;
            x_t[(4 * i + 1) * XPITCH + tid] = v.y;
            x_t[(4 * i + 2) * XPITCH + tid] = v.z;
            x_t[(4 * i + 3) * XPITCH + tid] = v.w;
        }
    }

    const int colx = wid * 32 + rx * 8;  // x_t column base (this thread's 8 rows)
    const int cole = cy * 8;             // e_t column base (this thread's 8 codes)

    float bm[8];
    int   bi[8];
#pragma unroll
    for (int r = 0; r < 8; ++r) { bm[r] = -3.4e38f; bi[r] = 0; }

    for (int tile = 0; tile < NTILES; ++tile) {
        __syncthreads();   // previous-tile reads done (and x_t visible on tile 0)
        {
            const float4* esrc = reinterpret_cast<const float4*>(
                embed + (size_t)(tile * TCODES + tid) * DIM);
#pragma unroll
            for (int i = 0; i < DIM / 4; ++i) {
                float4 v = esrc[i];
                e_t[(4 * i + 0) * EPITCH + tid] = v.x;
                e_t[(4 * i + 1) * EPITCH + tid] = v.y;
                e_t[(4 * i + 2) * EPITCH + tid] = v.z;
                e_t[(4 * i + 3) * EPITCH + tid] = v.w;
            }
        }
        __syncthreads();

        unsigned long long acc[8][4];
#pragma unroll
        for (int r = 0; r < 8; ++r)
#pragma unroll
            for (int c = 0; c < 4; ++c) acc[r][c] = 0ull;

#pragma unroll 2
        for (int k = 0; k < DIM; ++k) {
            const float* xr = &x_t[k * XPITCH + colx];
            float4 xa = *reinterpret_cast<const float4*>(xr);
            float4 xb = *reinterpret_cast<const float4*>(xr + 4);
            unsigned long long xd[8];
            xd[0] = pack_dup(xa.x); xd[1] = pack_dup(xa.y);
            xd[2] = pack_dup(xa.z); xd[3] = pack_dup(xa.w);
            xd[4] = pack_dup(xb.x); xd[5] = pack_dup(xb.y);
            xd[6] = pack_dup(xb.z); xd[7] = pack_dup(xb.w);

            const ulonglong2* ep = reinterpret_cast<const ulonglong2*>(
                &e_t[k * EPITCH + cole]);
            ulonglong2 e01 = ep[0], e23 = ep[1];
            unsigned long long e2[4] = {e01.x, e01.y, e23.x, e23.y};

#pragma unroll
            for (int r = 0; r < 8; ++r)
#pragma unroll
                for (int c = 0; c < 4; ++c)
                    fma2(acc[r][c], xd[r], e2[c]);
        }

        // Scores: m = dot - 0.5*||e||^2 (maximize). hn holds -0.5*||e||^2 packed pairs.
        const unsigned long long* hn = reinterpret_cast<const unsigned long long*>(
            g_hne + tile * TCODES + cole);
        unsigned long long h2[4] = {hn[0], hn[1], hn[2], hn[3]};
        const int cbase = tile * TCODES + cole;
#pragma unroll
        for (int r = 0; r < 8; ++r) {
#pragma unroll
            for (int c = 0; c < 4; ++c) {
                float2 m = unpack2(add2(acc[r][c], h2[c]));
                if (m.x > bm[r]) { bm[r] = m.x; bi[r] = cbase + 2 * c; }
                if (m.y > bm[r]) { bm[r] = m.y; bi[r] = cbase + 2 * c + 1; }
            }
        }
    }

    // Cross-thread argmax reduction over the 8 code-groups (lanes differing in cy).
#pragma unroll
    for (int r = 0; r < 8; ++r) {
#pragma unroll
        for (int off = 4; off < 32; off <<= 1) {
            float om = __shfl_xor_sync(0xffffffffu, bm[r], off);
            int   oi = __shfl_xor_sync(0xffffffffu, bi[r], off);
            if (om > bm[r] || (om == bm[r] && oi < bi[r])) { bm[r] = om; bi[r] = oi; }
        }
    }
    if (lane < 4) {
#pragma unroll
        for (int r = 0; r < 8; ++r)
            s_bidx[wid * 32 + lane * 8 + r] = bi[r];
    }
    __syncwarp();

    // Epilogue: one row per lane.
    const int rowl = wid * 32 + lane;
    const int grow = row0 + rowl;
    const int idx  = s_bidx[rowl];

    float sq = 0.f;
    {
        const float4* q = reinterpret_cast<const float4*>(embed + (size_t)idx * DIM);
        float4* o = reinterpret_cast<float4*>(out + (size_t)grow * DIM);
#pragma unroll
        for (int i = 0; i < DIM / 4; ++i) {
            float4 e = q[i];
            float x0 = x_t[(4 * i + 0) * XPITCH + rowl];
            float x1 = x_t[(4 * i + 1) * XPITCH + rowl];
            float x2 = x_t[(4 * i + 2) * XPITCH + rowl];
            float x3 = x_t[(4 * i + 3) * XPITCH + rowl];
            float d0 = e.x - x0, d1 = e.y - x1, d2 = e.z - x2, d3 = e.w - x3;
            sq += d0 * d0 + d1 * d1 + d2 * d2 + d3 * d3;
            o[i] = make_float4(x0 + d0, x1 + d1, x2 + d2, x3 + d3);
        }
    }
    out[(size_t)N_ROWS * DIM + grow] = (float)idx;

    // Deterministic block loss reduction.
    s_red[tid] = sq;
    __syncthreads();
#pragma unroll
    for (int s = THREADS / 2; s > 0; s >>= 1) {
        if (tid < s) s_red[tid] += s_red[tid + s];
        __syncthreads();
    }
    if (tid == 0) g_partial[blockIdx.x] = s_red[0];
}

// ---- kernel 3: finalize vq_loss = 1.25 * sum / (N*D) ----
__global__ void vq_finalize_kernel(float* __restrict__ out) {
    __shared__ float s[NBLOCKS];
    s[threadIdx.x] = g_partial[threadIdx.x];
    __syncthreads();
#pragma unroll
    for (int st = NBLOCKS / 2; st > 0; st >>= 1) {
        if (threadIdx.x < st) s[threadIdx.x] += s[threadIdx.x + st];
        __syncthreads();
    }
    if (threadIdx.x == 0) {
        out[(size_t)N_ROWS * DIM + N_ROWS] =
            1.25f * s[0] / (float)((size_t)N_ROWS * DIM);
    }
}

extern "C" void kernel_launch(void* const* d_in, const int* in_sizes, int n_in,
                              void* d_out, int out_size) {
    const float* z_e   = (const float*)d_in[0];
    const float* embed = (const float*)d_in[1];
    float* out = (float*)d_out;
    (void)in_sizes; (void)n_in; (void)out_size;

    vq_norms_kernel<<<KCODES / 256, 256>>>(embed);
    vq_main_kernel<<<NBLOCKS, THREADS>>>(z_e, embed, out);
    vq_finalize_kernel<<<1, NBLOCKS>>>(out);
}

// round 4
// speedup vs baseline: 2.2112x; 2.1213x over previous
#include <cuda_runtime.h>
#include <cuda_bf16.h>
#include <cstdint>

// Problem constants: z_e (16,4096,64) f32, embed (1024,64) f32.
#define N_ROWS  65536
#define DIM     64
#define KCODES  1024
#define M_CTA   128
#define NT      64                   // codes per tile
#define NTILES  (KCODES / NT)        // 16
#define THREADS 256
#define NBLOCKS (N_ROWS / M_CTA)     // 512
#define DELTA   0.008f

// smem byte offsets within dynamic smem
#define SM_HNE    0        // 1024 floats  (4096 B)
#define SM_CNT    4096
#define SM_FLAG   4112     // 128 ints
#define SM_ROWIDX 4624     // 128 ints
#define SM_RED    5184     // float[256] + int[256] = 2048 B
#define SM_X      8192     // Xhi 16K + Xlo 16K
#define SM_B      40960    // 2 bufs x (Ehi 8K + Elo 8K) = 32K
#define SMEM_BYTES 73728

__device__ float g_hne[KCODES];          // -0.5 * ||e_k||^2
__device__ float g_partial[NBLOCKS];
__device__ uint4 g_ehi4[KCODES * 8];     // E hi bf16, [code][64] row-major (128B/row)
__device__ uint4 g_elo4[KCODES * 8];     // E lo bf16

// ===================== helpers =====================
__device__ __forceinline__ uint32_t smem_to_u32(const void* p) {
    uint32_t a;
    asm("{ .reg .u64 t; cvta.to.shared.u64 t, %1; cvt.u32.u64 %0, t; }"
        : "=r"(a) : "l"(p));
    return a;
}

__device__ __forceinline__ uint32_t pack_bf2(float a, float b, float& ra, float& rb) {
    __nv_bfloat16 ha = __float2bfloat16_rn(a);
    __nv_bfloat16 hb = __float2bfloat16_rn(b);
    ra = a - __bfloat162float(ha);
    rb = b - __bfloat162float(hb);
    return (uint32_t)__bfloat16_as_ushort(ha) |
           ((uint32_t)__bfloat16_as_ushort(hb) << 16);
}

#define LDSM4(r, addr) \
    asm volatile("ldmatrix.sync.aligned.m8n8.x4.shared.b16 {%0,%1,%2,%3}, [%4];" \
        : "=r"((r)[0]), "=r"((r)[1]), "=r"((r)[2]), "=r"((r)[3]) : "r"(addr))

#define MMA16816(d, a, b0_, b1_) \
    asm volatile("mma.sync.aligned.m16n8k16.row.col.f32.bf16.bf16.f32 " \
        "{%0,%1,%2,%3}, {%4,%5,%6,%7}, {%8,%9}, {%0,%1,%2,%3};" \
        : "+f"((d)[0]), "+f"((d)[1]), "+f"((d)[2]), "+f"((d)[3]) \
        : "r"((a)[0]), "r"((a)[1]), "r"((a)[2]), "r"((a)[3]), "r"(b0_), "r"(b1_))

#define CP_ASYNC16(dst, src) \
    asm volatile("cp.async.cg.shared.global [%0], [%1], 16;" \
        :: "r"(dst), "l"(src) : "memory")
#define CP_COMMIT() asm volatile("cp.async.commit_group;" ::: "memory")
#define CP_WAIT1()  asm volatile("cp.async.wait_group 1;" ::: "memory")
#define CP_WAIT0()  asm volatile("cp.async.wait_group 0;" ::: "memory")

// ===================== kernel 1: prep (norms + bf16 split of E) ============
__global__ void vq_prep_kernel(const float* __restrict__ embed) {
    int k = blockIdx.x * blockDim.x + threadIdx.x;   // 0..1023
    if (k >= KCODES) return;
    const float4* e4 = reinterpret_cast<const float4*>(embed + (size_t)k * DIM);
    float s = 0.f;
#pragma unroll
    for (int j = 0; j < 8; ++j) {
        float4 v0 = e4[2 * j], v1 = e4[2 * j + 1];
        s += v0.x * v0.x + v0.y * v0.y + v0.z * v0.z + v0.w * v0.w +
             v1.x * v1.x + v1.y * v1.y + v1.z * v1.z + v1.w * v1.w;
        float r0, r1, r2, r3, r4, r5, r6, r7;
        uint32_t h0 = pack_bf2(v0.x, v0.y, r0, r1);
        uint32_t h1 = pack_bf2(v0.z, v0.w, r2, r3);
        uint32_t h2 = pack_bf2(v1.x, v1.y, r4, r5);
        uint32_t h3 = pack_bf2(v1.z, v1.w, r6, r7);
        float d0, d1;
        uint32_t l0 = pack_bf2(r0, r1, d0, d1);
        uint32_t l1 = pack_bf2(r2, r3, d0, d1);
        uint32_t l2 = pack_bf2(r4, r5, d0, d1);
        uint32_t l3 = pack_bf2(r6, r7, d0, d1);
        g_ehi4[k * 8 + j] = make_uint4(h0, h1, h2, h3);
        g_elo4[k * 8 + j] = make_uint4(l0, l1, l2, l3);
    }
    g_hne[k] = -0.5f * s;
}

// ===================== kernel 2: main =====================
__device__ __forceinline__ void stage_tile(uint32_t smem_base, int buf, int t, int tid) {
    const char* ghi = reinterpret_cast<const char*>(g_ehi4);
    const char* glo = reinterpret_cast<const char*>(g_elo4);
#pragma unroll
    for (int cc = 0; cc < 2; ++cc) {
        int c = tid + cc * 256;                       // chunk 0..511
        uint32_t rowb = (uint32_t)(c >> 3) * 128u;
        uint32_t col  = ((uint32_t)(c & 7) * 16u) ^ ((((uint32_t)c >> 3) & 7u) << 4);
        uint32_t dst = smem_base + SM_B + (uint32_t)buf * 16384u + rowb + col;
        const char* srch = ghi + ((size_t)t * 512 + c) * 16;
        const char* srcl = glo + ((size_t)t * 512 + c) * 16;
        CP_ASYNC16(dst, srch);
        CP_ASYNC16(dst + 8192, srcl);
    }
}

__global__ __launch_bounds__(THREADS, 2)
void vq_main_kernel(const float* __restrict__ z_e,
                    const float* __restrict__ embed,
                    float* __restrict__ out) {
    extern __shared__ char smem[];
    const uint32_t smem_base = smem_to_u32(smem);

    const int tid  = threadIdx.x;
    const int lane = tid & 31;
    const int wid  = tid >> 5;
    const int row0 = blockIdx.x * M_CTA;

    float* s_hne    = reinterpret_cast<float*>(smem + SM_HNE);
    int*   s_cnt    = reinterpret_cast<int*>(smem + SM_CNT);
    int*   s_flag   = reinterpret_cast<int*>(smem + SM_FLAG);
    int*   s_rowidx = reinterpret_cast<int*>(smem + SM_ROWIDX);
    float* s_rm     = reinterpret_cast<float*>(smem + SM_RED);
    int*   s_ri     = reinterpret_cast<int*>(smem + SM_RED + 1024);

    // Prefetch code tiles 0 and 1 (overlaps with X staging below).
    stage_tile(smem_base, 0, 0, tid); CP_COMMIT();
    stage_tile(smem_base, 1, 1, tid); CP_COMMIT();

    if (tid == 0) *s_cnt = 0;

    // Stage X (128 rows): split fp32 -> bf16 hi/lo, swizzled smem.
    {
        const int xrow = tid >> 1;
        const int hf   = tid & 1;
        const float4* xs = reinterpret_cast<const float4*>(
            z_e + (size_t)(row0 + xrow) * DIM + hf * 32);
        const uint32_t xxor = ((uint32_t)xrow & 7u) << 4;
#pragma unroll
        for (int j = 0; j < 4; ++j) {
            float4 v0 = xs[2 * j], v1 = xs[2 * j + 1];
            float r0, r1, r2, r3, r4, r5, r6, r7;
            uint32_t h0 = pack_bf2(v0.x, v0.y, r0, r1);
            uint32_t h1 = pack_bf2(v0.z, v0.w, r2, r3);
            uint32_t h2 = pack_bf2(v1.x, v1.y, r4, r5);
            uint32_t h3 = pack_bf2(v1.z, v1.w, r6, r7);
            float d0, d1;
            uint32_t l0 = pack_bf2(r0, r1, d0, d1);
            uint32_t l1 = pack_bf2(r2, r3, d0, d1);
            uint32_t l2 = pack_bf2(r4, r5, d0, d1);
            uint32_t l3 = pack_bf2(r6, r7, d0, d1);
            uint32_t col = ((uint32_t)(hf * 64 + j * 16)) ^ xxor;
            *reinterpret_cast<uint4*>(smem + SM_X + xrow * 128 + col) =
                make_uint4(h0, h1, h2, h3);
            *reinterpret_cast<uint4*>(smem + SM_X + 16384 + xrow * 128 + col) =
                make_uint4(l0, l1, l2, l3);
        }
    }
    // Stage hne.
#pragma unroll
    for (int i = 0; i < 4; ++i) s_hne[tid + i * 256] = g_hne[tid + i * 256];
    __syncthreads();

    // A fragments (persist across all tiles): hi + lo, 4 k-chunks.
    uint32_t ah[4][4], al[4][4];
    {
        const uint32_t arow = (uint32_t)(wid * 16 + (lane & 15));
        const uint32_t acs  = (uint32_t)(lane & 16);
        const uint32_t axor = (arow & 7u) << 4;
        const uint32_t abhi = smem_base + SM_X + arow * 128u;
#pragma unroll
        for (int kc = 0; kc < 4; ++kc) {
            uint32_t col = (((uint32_t)(kc * 32)) | acs) ^ axor;
            LDSM4(ah[kc], abhi + col);
            LDSM4(al[kc], abhi + 16384u + col);
        }
    }

    // B address pattern.
    const uint32_t bco  = (uint32_t)((lane & 7) + ((lane & 16) >> 1));
    const uint32_t bcs  = (uint32_t)((lane & 8) << 1);
    const uint32_t bxor = (bco & 7u) << 4;

    float m1l = -3.4e38f, m2l = -3.4e38f, m1h = -3.4e38f, m2h = -3.4e38f;
    int   i1l = 0, i1h = 0;

#pragma unroll 1
    for (int t = 0; t < NTILES; ++t) {
        if (t < NTILES - 1) CP_WAIT1(); else CP_WAIT0();
        __syncthreads();
        const int buf = t & 1;

        float acc[8][4];
#pragma unroll
        for (int nb = 0; nb < 8; ++nb)
#pragma unroll
            for (int q = 0; q < 4; ++q) acc[nb][q] = 0.f;

        const uint32_t bbase = smem_base + SM_B + (uint32_t)buf * 16384u + bco * 128u;
#pragma unroll
        for (int kc = 0; kc < 4; ++kc) {
            const uint32_t col = (((uint32_t)(kc * 32)) | bcs) ^ bxor;
#pragma unroll
            for (int p = 0; p < 4; ++p) {
                uint32_t addr = bbase + (uint32_t)(p * 2048) + col;
                uint32_t bh[4], bl[4];
                LDSM4(bh, addr);
                LDSM4(bl, addr + 8192u);
                MMA16816(acc[2 * p],     ah[kc], bh[0], bh[1]);
                MMA16816(acc[2 * p + 1], ah[kc], bh[2], bh[3]);
                MMA16816(acc[2 * p],     ah[kc], bl[0], bl[1]);
                MMA16816(acc[2 * p + 1], ah[kc], bl[2], bl[3]);
                MMA16816(acc[2 * p],     al[kc], bh[0], bh[1]);
                MMA16816(acc[2 * p + 1], al[kc], bh[2], bh[3]);
            }
        }

        // Score update (top1/top2 per row).
        const int cb0 = t * NT + (lane & 3) * 2;
#pragma unroll
        for (int nb = 0; nb < 8; ++nb) {
            const int cb = cb0 + nb * 8;
            float2 h2 = *reinterpret_cast<const float2*>(&s_hne[cb]);
            float s0 = acc[nb][0] + h2.x;
            float s1 = acc[nb][1] + h2.y;
            float s2 = acc[nb][2] + h2.x;
            float s3 = acc[nb][3] + h2.y;
            if (s0 > m1l) { m2l = m1l; m1l = s0; i1l = cb; }
            else if (s0 > m2l) m2l = s0;
            if (s1 > m1l) { m2l = m1l; m1l = s1; i1l = cb + 1; }
            else if (s1 > m2l) m2l = s1;
            if (s2 > m1h) { m2h = m1h; m1h = s2; i1h = cb; }
            else if (s2 > m2h) m2h = s2;
            if (s3 > m1h) { m2h = m1h; m1h = s3; i1h = cb + 1; }
            else if (s3 > m2h) m2h = s3;
        }
        __syncthreads();
        if (t + 2 < NTILES) { stage_tile(smem_base, buf, t + 2, tid); CP_COMMIT(); }
    }

    // Merge top1/top2 across the 4 lanes sharing each row.
#pragma unroll
    for (int off = 1; off <= 2; off <<= 1) {
        float om1 = __shfl_xor_sync(0xffffffffu, m1l, off);
        float om2 = __shfl_xor_sync(0xffffffffu, m2l, off);
        int   oi  = __shfl_xor_sync(0xffffffffu, i1l, off);
        if (om1 > m1l || (om1 == m1l && oi < i1l)) {
            m2l = fmaxf(m1l, om2); m1l = om1; i1l = oi;
        } else m2l = fmaxf(m2l, om1);
        om1 = __shfl_xor_sync(0xffffffffu, m1h, off);
        om2 = __shfl_xor_sync(0xffffffffu, m2h, off);
        oi  = __shfl_xor_sync(0xffffffffu, i1h, off);
        if (om1 > m1h || (om1 == m1h && oi < i1h)) {
            m2h = fmaxf(m1h, om2); m1h = om1; i1h = oi;
        } else m2h = fmaxf(m2h, om1);
    }
    if ((lane & 3) == 0) {
        const int rlo = wid * 16 + (lane >> 2);
        s_rowidx[rlo] = i1l;
        s_rowidx[rlo + 8] = i1h;
        if (m1l - m2l <= DELTA) { int p = atomicAdd(s_cnt, 1); s_flag[p] = rlo; }
        if (m1h - m2h <= DELTA) { int p = atomicAdd(s_cnt, 1); s_flag[p] = rlo + 8; }
    }
    __syncthreads();

    // Rare exact fp32 rescan for flagged rows (CTA-cooperative).
    const int nf = *s_cnt;
    for (int f = 0; f < nf; ++f) {
        const int r = s_flag[f];
        const float4* x4 = reinterpret_cast<const float4*>(
            z_e + (size_t)(row0 + r) * DIM);
        float xv[DIM];
#pragma unroll
        for (int i = 0; i < DIM / 4; ++i) {
            float4 v = x4[i];
            xv[4 * i] = v.x; xv[4 * i + 1] = v.y;
            xv[4 * i + 2] = v.z; xv[4 * i + 3] = v.w;
        }
        float bm = -3.4e38f; int bidx = 0;
#pragma unroll 1
        for (int c0 = 0; c0 < 4; ++c0) {
            int c = tid * 4 + c0;
            const float4* e4 = reinterpret_cast<const float4*>(
                embed + (size_t)c * DIM);
            float dot = 0.f;
#pragma unroll
            for (int i = 0; i < DIM / 4; ++i) {
                float4 e = e4[i];
                dot += xv[4 * i] * e.x + xv[4 * i + 1] * e.y +
                       xv[4 * i + 2] * e.z + xv[4 * i + 3] * e.w;
            }
            float m = dot + s_hne[c];
            if (m > bm) { bm = m; bidx = c; }
        }
        s_rm[tid] = bm; s_ri[tid] = bidx;
        __syncthreads();
#pragma unroll
        for (int s = 128; s > 0; s >>= 1) {
            if (tid < s) {
                float om = s_rm[tid + s]; int oi = s_ri[tid + s];
                if (om > s_rm[tid] || (om == s_rm[tid] && oi < s_ri[tid])) {
                    s_rm[tid] = om; s_ri[tid] = oi;
                }
            }
            __syncthreads();
        }
        if (tid == 0) s_rowidx[r] = s_ri[0];
        __syncthreads();
    }

    // Epilogue: gather + straight-through + per-row loss.
    float sq = 0.f;
    if (tid < 128) {
        const int grow = row0 + tid;
        const int idx = s_rowidx[tid];
        const float4* q  = reinterpret_cast<const float4*>(embed + (size_t)idx * DIM);
        const float4* x4 = reinterpret_cast<const float4*>(z_e + (size_t)grow * DIM);
        float4* o = reinterpret_cast<float4*>(out + (size_t)grow * DIM);
#pragma unroll
        for (int i = 0; i < DIM / 4; ++i) {
            float4 e = q[i];
            float4 x = x4[i];
            float d0 = e.x - x.x, d1 = e.y - x.y, d2 = e.z - x.z, d3 = e.w - x.w;
            sq += d0 * d0 + d1 * d1 + d2 * d2 + d3 * d3;
            o[i] = make_float4(x.x + d0, x.y + d1, x.z + d2, x.w + d3);
        }
        out[(size_t)N_ROWS * DIM + grow] = (float)idx;
    }

    s_rm[tid] = sq;
    __syncthreads();
#pragma unroll
    for (int s = 128; s > 0; s >>= 1) {
        if (tid < s) s_rm[tid] += s_rm[tid + s];
        __syncthreads();
    }
    if (tid == 0) g_partial[blockIdx.x] = s_rm[0];
}

// ===================== kernel 3: finalize =====================
__global__ void vq_finalize_kernel(float* __restrict__ out) {
    __shared__ float s[NBLOCKS];
    s[threadIdx.x] = g_partial[threadIdx.x];
    __syncthreads();
#pragma unroll
    for (int st = NBLOCKS / 2; st > 0; st >>= 1) {
        if (threadIdx.x < st) s[threadIdx.x] += s[threadIdx.x + st];
        __syncthreads();
    }
    if (threadIdx.x == 0)
        out[(size_t)N_ROWS * DIM + N_ROWS] =
            1.25f * s[0] / (float)((size_t)N_ROWS * DIM);
}

extern "C" void kernel_launch(void* const* d_in, const int* in_sizes, int n_in,
                              void* d_out, int out_size) {
    const float* z_e   = (const float*)d_in[0];
    const float* embed = (const float*)d_in[1];
    float* out = (float*)d_out;
    (void)in_sizes; (void)n_in; (void)out_size;

    cudaFuncSetAttribute(vq_main_kernel,
                         cudaFuncAttributeMaxDynamicSharedMemorySize, SMEM_BYTES);

    vq_prep_kernel<<<KCODES / 256, 256>>>(embed);
    vq_main_kernel<<<NBLOCKS, THREADS, SMEM_BYTES>>>(z_e, embed, out);
    vq_finalize_kernel<<<1, NBLOCKS>>>(out);
}